// round 15
// baseline (speedup 1.0000x reference)
#include <cuda_runtime.h>
#include <cuda_bf16.h>
#include <cstdint>

// ============================================================================
// VQ via mma.sync bf16 (m16n8k16). 148 persistent CTAs (256 threads), queue of
// 1024 (128-token block, quarter) items. 8 warps x (32x64) tiles, DOUBLE-
// BUFFERED accumulators: epilogue of tile t-1 executes under the MMAs of
// tile t. A + B via cp.async.bulk from PRE-SWIZZLED images. Exact
// sequential-fp32-FMA-chain recheck (bit-identical to reference).
// ============================================================================

#define TOKENS   32768
#define HID      256
#define NCODES   8192
#define MT       128
#define NTILE    128
#define QCODES   2048
#define TPI      16                   // tiles per item
#define NITEMS   1024                 // 256 m-blocks * 4 quarters
#define CAPQ     64
#define DELTA    0.03f
#define Z_ST_ELEMS (TOKENS * HID)
#define FULL_OUT   (Z_ST_ELEMS + TOKENS + 2)

typedef unsigned long long ull;

__device__ __align__(128) unsigned char g_zsw[TOKENS * 512];    // 16MB
__device__ __align__(128) unsigned char g_etile[NCODES * 512];  // 4MB
__device__ float    g_e2[NCODES];
__device__ float    g_z2[TOKENS];
__device__ unsigned g_cc4[TOKENS * 4];
__device__ unsigned short g_cd[TOKENS * 4 * CAPQ];
__device__ int      g_queue;
__device__ double   g_loss;

// ---- SMEM layout ----
#define A_OFF   0                        // 128*512 = 65536
#define B_OFF   65536                    // 2 * 65536 -> 196608
#define E2S_OFF 196608                   // 2048 f32 = 8192
#define MKP_OFF 204800                   // 2 parity * 2 warpN * 128 f32 = 2048
#define MB_OFF  206848                   // 3 mbarriers
#define SITEM   206872
#define SMEM_BYTES 206880

// ---- PTX helpers ----
__device__ __forceinline__ uint32_t smem_u32(const void* p) {
    uint32_t a;
    asm("{ .reg .u64 t; cvta.to.shared.u64 t, %1; cvt.u32.u64 %0, t; }"
        : "=r"(a) : "l"(p));
    return a;
}
__device__ __forceinline__ void cp_async16(uint32_t dst, const void* src) {
    asm volatile("cp.async.cg.shared.global [%0], [%1], 16;\n"
                 :: "r"(dst), "l"(src));
}
#define CP_COMMIT() asm volatile("cp.async.commit_group;" ::: "memory")
#define CP_WAIT0()  asm volatile("cp.async.wait_group 0;" ::: "memory")
#define FENCE_ASYNC() asm volatile("fence.proxy.async.shared::cta;" ::: "memory")

#define MBARRIER_INIT(a, c) \
    asm volatile("mbarrier.init.shared.b64 [%0], %1;" \
                 :: "r"((uint32_t)(a)), "r"((uint32_t)(c)) : "memory")
#define MBAR_EXPECT(bar, tx) \
    asm volatile("mbarrier.arrive.expect_tx.shared.b64 _, [%0], %1;" \
                 :: "r"((uint32_t)(bar)), "r"((uint32_t)(tx)) : "memory")
#define BULK_G2S(dst, src, sz, bar) \
    asm volatile("cp.async.bulk.shared::cta.global.mbarrier::complete_tx::bytes " \
                 "[%0], [%1], %2, [%3];" \
                 :: "r"((uint32_t)(dst)), "l"(src), "r"((uint32_t)(sz)), \
                    "r"((uint32_t)(bar)) : "memory")
#define MBARRIER_WAIT_PARITY(addr, par) do { \
    uint32_t _m = (uint32_t)(addr), _p = (uint32_t)(par), _d; \
    asm volatile("{\n\t.reg .pred p;\n\t" \
        "mbarrier.try_wait.parity.acquire.cta.shared::cta.b64 p, [%1], %2;\n\t" \
        "selp.b32 %0, 1, 0, p;\n\t}" : "=r"(_d) : "r"(_m), "r"(_p) : "memory"); \
    if (!_d) { \
        asm volatile("{\n\t.reg .pred P1;\n\t" \
            "W%=:\n\t" \
            "mbarrier.try_wait.parity.acquire.cta.shared::cta.b64 P1, [%0], %1, 0x989680;\n\t" \
            "@P1 bra.uni D%=;\n\t" \
            "bra.uni W%=;\n\t" \
            "D%=:\n\t}" :: "r"(_m), "r"(_p) : "memory"); \
    } \
} while (0)

#define LDSM4(r, a) \
    asm volatile("ldmatrix.sync.aligned.m8n8.x4.shared.b16 {%0,%1,%2,%3}, [%4];" \
        : "=r"((r)[0]), "=r"((r)[1]), "=r"((r)[2]), "=r"((r)[3]) : "r"(a))

#define MMA16816(d, a, b0, b1) \
    asm volatile("mma.sync.aligned.m16n8k16.row.col.f32.bf16.bf16.f32 " \
        "{%0,%1,%2,%3}, {%4,%5,%6,%7}, {%8,%9}, {%0,%1,%2,%3};" \
        : "+f"((d)[0]), "+f"((d)[1]), "+f"((d)[2]), "+f"((d)[3]) \
        : "r"((a)[0]), "r"((a)[1]), "r"((a)[2]), "r"((a)[3]), "r"(b0), "r"(b1))

__device__ __forceinline__ unsigned fkey(float f) {
    unsigned u = __float_as_uint(f);
    return (u & 0x80000000u) ? ~u : (u | 0x80000000u);
}
__device__ __forceinline__ unsigned pk2(float a, float b) {
    __nv_bfloat162 t = __floats2bfloat162_rn(a, b);
    return *(unsigned*)&t;
}
// exact sequential fp32 FMA chain over ascending k (reference arithmetic)
__device__ __forceinline__ float exact_dot(const float4* zr, const float4* er) {
    float dot = 0.f;
    #pragma unroll 8
    for (int kk = 0; kk < HID / 4; ++kk) {
        float4 a = zr[kk], b = er[kk];
        dot = fmaf(a.x, b.x, dot);
        dot = fmaf(a.y, b.y, dot);
        dot = fmaf(a.z, b.z, dot);
        dot = fmaf(a.w, b.w, dot);
    }
    return dot;
}

// ---- init (launch #1) ----
__global__ void init_kernel() {
    int i = blockIdx.x * 256 + threadIdx.x;
    g_cc4[i] = 0u;
    if (i == 0) { g_queue = 0; g_loss = 0.0; }
}

// ---- prep kernels: bf16 convert + PRE-SWIZZLE (128-row blocks) + norms ----
__global__ void prep_e(const float* __restrict__ emb) {
    int code = blockIdx.x * 8 + (threadIdx.x >> 5);
    int lane = threadIdx.x & 31;
    const float4* r = (const float4*)(emb + (size_t)code * HID);
    float4 v0 = r[lane * 2], v1 = r[lane * 2 + 1];
    double s = (double)v0.x * v0.x + (double)v0.y * v0.y +
               (double)v0.z * v0.z + (double)v0.w * v0.w +
               (double)v1.x * v1.x + (double)v1.y * v1.y +
               (double)v1.z * v1.z + (double)v1.w * v1.w;
    #pragma unroll
    for (int o = 16; o; o >>= 1) s += __shfl_down_sync(0xffffffffu, s, o);
    if (lane == 0) g_e2[code] = (float)s;
    uint4 pk = make_uint4(pk2(v0.x, v0.y), pk2(v0.z, v0.w),
                          pk2(v1.x, v1.y), pk2(v1.z, v1.w));
    int tt = code >> 7, rr = code & 127;
    *(uint4*)(g_etile + (size_t)tt * 65536 + rr * 512 +
              ((lane ^ (rr & 7)) << 4)) = pk;
}
__global__ void prep_z(const float* __restrict__ z) {
    int tok = blockIdx.x * 8 + (threadIdx.x >> 5);
    int lane = threadIdx.x & 31;
    const float4* r = (const float4*)(z + (size_t)tok * HID);
    float4 v0 = r[lane * 2], v1 = r[lane * 2 + 1];
    double s = (double)v0.x * v0.x + (double)v0.y * v0.y +
               (double)v0.z * v0.z + (double)v0.w * v0.w +
               (double)v1.x * v1.x + (double)v1.y * v1.y +
               (double)v1.z * v1.z + (double)v1.w * v1.w;
    #pragma unroll
    for (int o = 16; o; o >>= 1) s += __shfl_down_sync(0xffffffffu, s, o);
    if (lane == 0) g_z2[tok] = (float)s;
    uint4 pk = make_uint4(pk2(v0.x, v0.y), pk2(v0.z, v0.w),
                          pk2(v1.x, v1.y), pk2(v1.z, v1.w));
    int bb = tok >> 7, rr = tok & 127;
    *(uint4*)(g_zsw + (size_t)bb * 65536 + rr * 512 +
              ((lane ^ (rr & 7)) << 4)) = pk;
}

// ---- main persistent kernel (launch #4) -------------------------------------
__global__ void __launch_bounds__(256, 1)
vq_mma() {
    extern __shared__ char p0[];
    const uint32_t s0 = smem_u32(p0);

    const int tid = threadIdx.x;
    const int lane = tid & 31, wid = tid >> 5;
    const int warpM = wid >> 1, warpN = wid & 1;     // 4M x 2N, warp = 32x64
    const int g = lane >> 2, tg = lane & 3;
    int* sitem = (int*)(p0 + SITEM);
    float* e2s = (float*)(p0 + E2S_OFF);
    float* mkp = (float*)(p0 + MKP_OFF);             // [parity][warpN][128]
    const uint32_t mbA  = s0 + MB_OFF;
    const uint32_t mbB0 = s0 + MB_OFF + 8;
    const uint32_t mbB1 = s0 + MB_OFF + 16;

    if (tid == 0) {
        MBARRIER_INIT(mbA, 1);
        MBARRIER_INIT(mbB0, 1);
        MBARRIER_INIT(mbB1, 1);
    }
    __syncthreads();
    FENCE_ASYNC();

    const int r7 = lane & 7, cc = lane >> 4;
    const uint32_t aBase = s0 + A_OFF + (warpM * 32 + (lane & 15)) * 512;
    const uint32_t bBase = s0 + B_OFF + (warpN * 64 + (lane & 15)) * 512;

    int curm = -1, aPar = 0;
    float z2r[4];
    int rowid[4];
    float accA[2][8][4], accB[2][8][4];

    for (;;) {
        __syncthreads();                 // previous item fully consumed
        if (tid == 0) *sitem = atomicAdd(&g_queue, 1);
        __syncthreads();
        const int item = *sitem;
        if (item >= NITEMS) break;
        const int m = item >> 2, q = item & 3;

        const bool newm = (m != curm);
        if (newm) {
            curm = m;
            if (tid == 0) {
                MBAR_EXPECT(mbA, 65536);
                BULK_G2S(s0 + A_OFF, g_zsw + (size_t)m * 65536, 65536, mbA);
            }
            #pragma unroll
            for (int r4 = 0; r4 < 4; ++r4) {
                int row = warpM * 32 + (r4 >> 1) * 16 + (r4 & 1) * 8 + g;
                rowid[r4] = m * MT + row;
                z2r[r4] = g_z2[rowid[r4]];
            }
        }
        // e2 quarter slice + first two B tiles
        cp_async16(s0 + E2S_OFF + tid * 32,
                   (const char*)(g_e2 + q * QCODES) + tid * 32);
        cp_async16(s0 + E2S_OFF + tid * 32 + 16,
                   (const char*)(g_e2 + q * QCODES) + tid * 32 + 16);
        CP_COMMIT();
        if (tid == 0) {
            MBAR_EXPECT(mbB0, 65536);
            BULK_G2S(s0 + B_OFF, g_etile + (size_t)(q * TPI) * 65536,
                     65536, mbB0);
            MBAR_EXPECT(mbB1, 65536);
            BULK_G2S(s0 + B_OFF + 65536,
                     g_etile + (size_t)(q * TPI + 1) * 65536, 65536, mbB1);
        }
        CP_WAIT0();
        __syncthreads();                 // e2s visible to all threads
        if (newm) { MBARRIER_WAIT_PARITY(mbA, aPar); aPar ^= 1; }

        float rm[4];
        #pragma unroll
        for (int r4 = 0; r4 < 4; ++r4) rm[r4] = __int_as_float(0x7f800000);

        // ---- macro: issue full MMA chain for tile tt into ACC ----
        #define MMA_TILE(ACC, tt) do {                                        \
            _Pragma("unroll")                                                 \
            for (int a = 0; a < 2; ++a)                                       \
                _Pragma("unroll")                                             \
                for (int b = 0; b < 8; ++b)                                   \
                    _Pragma("unroll")                                         \
                    for (int c = 0; c < 4; ++c) ACC[a][b][c] = 0.f;           \
            const uint32_t bT = bBase + ((tt) & 1) * 65536;                   \
            _Pragma("unroll")                                                 \
            for (int ks = 0; ks < 16; ++ks) {                                 \
                const uint32_t off = (uint32_t)(((2 * ks + cc) ^ r7) << 4);   \
                uint32_t A0[4], A1[4], Bf0[4], Bf1[4], Bf2[4], Bf3[4];        \
                LDSM4(A0, aBase + off);                                       \
                LDSM4(A1, aBase + 8192 + off);                                \
                LDSM4(Bf0, bT + off);                                         \
                LDSM4(Bf1, bT + 8192 + off);                                  \
                LDSM4(Bf2, bT + 16384 + off);                                 \
                LDSM4(Bf3, bT + 24576 + off);                                 \
                MMA16816(ACC[0][0], A0, Bf0[0], Bf0[2]);                      \
                MMA16816(ACC[0][1], A0, Bf0[1], Bf0[3]);                      \
                MMA16816(ACC[0][2], A0, Bf1[0], Bf1[2]);                      \
                MMA16816(ACC[0][3], A0, Bf1[1], Bf1[3]);                      \
                MMA16816(ACC[0][4], A0, Bf2[0], Bf2[2]);                      \
                MMA16816(ACC[0][5], A0, Bf2[1], Bf2[3]);                      \
                MMA16816(ACC[0][6], A0, Bf3[0], Bf3[2]);                      \
                MMA16816(ACC[0][7], A0, Bf3[1], Bf3[3]);                      \
                MMA16816(ACC[1][0], A1, Bf0[0], Bf0[2]);                      \
                MMA16816(ACC[1][1], A1, Bf0[1], Bf0[3]);                      \
                MMA16816(ACC[1][2], A1, Bf1[0], Bf1[2]);                      \
                MMA16816(ACC[1][3], A1, Bf1[1], Bf1[3]);                      \
                MMA16816(ACC[1][4], A1, Bf2[0], Bf2[2]);                      \
                MMA16816(ACC[1][5], A1, Bf2[1], Bf2[3]);                      \
                MMA16816(ACC[1][6], A1, Bf3[0], Bf3[2]);                      \
                MMA16816(ACC[1][7], A1, Bf3[1], Bf3[3]);                      \
            }                                                                 \
        } while (0)

        // phase A for tile tp on ACC: dists + warp row-min -> mkp[tp&1]
        #define PHASE_A(ACC, tp, LM) do {                                     \
            _Pragma("unroll")                                                 \
            for (int mf = 0; mf < 2; ++mf)                                    \
                _Pragma("unroll")                                             \
                for (int h = 0; h < 2; ++h) {                                 \
                    const int r4 = mf * 2 + h;                                \
                    const float z2t = z2r[r4];                                \
                    float lmin = __int_as_float(0x7f800000);                  \
                    _Pragma("unroll")                                         \
                    for (int nf = 0; nf < 8; ++nf) {                          \
                        float2 ev = *(const float2*)&e2s[(tp) * NTILE +       \
                            warpN * 64 + nf * 8 + tg * 2];                    \
                        float d0 = fmaf(-2.f, ACC[mf][nf][h * 2], z2t) + ev.x;\
                        float d1 = fmaf(-2.f, ACC[mf][nf][h * 2 + 1], z2t)    \
                                   + ev.y;                                    \
                        ACC[mf][nf][h * 2] = d0;                              \
                        ACC[mf][nf][h * 2 + 1] = d1;                          \
                        lmin = fminf(lmin, fminf(d0, d1));                    \
                    }                                                         \
                    lmin = fminf(lmin, __shfl_xor_sync(0xffffffffu, lmin, 1));\
                    lmin = fminf(lmin, __shfl_xor_sync(0xffffffffu, lmin, 2));\
                    LM[r4] = lmin;                                            \
                    const int row = warpM * 32 + mf * 16 + h * 8 + g;         \
                    if (tg == 0)                                              \
                        mkp[((tp) & 1) * 256 + warpN * 128 + row] = lmin;     \
                }                                                             \
        } while (0)

        // phase B for tile tp on ACC: threshold + early-out candidate append
        #define PHASE_B(ACC, tp, LM) do {                                     \
            const float* mk0 = mkp + ((tp) & 1) * 256;                        \
            _Pragma("unroll")                                                 \
            for (int mf = 0; mf < 2; ++mf)                                    \
                _Pragma("unroll")                                             \
                for (int h = 0; h < 2; ++h) {                                 \
                    const int r4 = mf * 2 + h;                                \
                    const int row = warpM * 32 + mf * 16 + h * 8 + g;         \
                    float tmin = fminf(mk0[row], mk0[128 + row]);             \
                    rm[r4] = fminf(rm[r4], tmin);                             \
                    const float thr = rm[r4] + DELTA;                         \
                    if (LM[r4] <= thr) {                                      \
                        _Pragma("unroll")                                     \
                        for (int nf = 0; nf < 8; ++nf)                        \
                            _Pragma("unroll")                                 \
                            for (int e = 0; e < 2; ++e)                       \
                                if (ACC[mf][nf][h * 2 + e] <= thr) {          \
                                    unsigned pos = atomicAdd(                 \
                                        &g_cc4[rowid[r4] * 4 + q], 1u);       \
                                    if (pos < CAPQ)                           \
                                        g_cd[(rowid[r4] * 4 + q) * CAPQ + pos]\
                                            = (unsigned short)(q * QCODES +   \
                                                (tp) * NTILE + warpN * 64 +   \
                                                nf * 8 + tg * 2 + e);         \
                                }                                             \
                    }                                                         \
                }                                                             \
        } while (0)

        // ---- prologue: tile 0 ----
        MBARRIER_WAIT_PARITY(mbB0, 0);
        MMA_TILE(accA, 0);

        float lmA[4], lmB[4];
        for (int t = 1; t < TPI; ++t) {
            MBARRIER_WAIT_PARITY((t & 1) ? mbB1 : mbB0, (t >> 1) & 1);
            if (t & 1) {
                MMA_TILE(accB, t);                  // tensor busy with t
                PHASE_A(accA, t - 1, lmA);          // overlapped epilogue
            } else {
                MMA_TILE(accA, t);
                PHASE_A(accB, t - 1, lmB);
            }
            __syncthreads();                        // mkp ready; LDSM(t-1) done
            if (tid == 0 && t + 1 < TPI) {          // stage (t+1)&1 now free
                const uint32_t bar = (t & 1) ? mbB0 : mbB1;
                MBAR_EXPECT(bar, 65536);
                BULK_G2S(s0 + B_OFF + ((t + 1) & 1) * 65536,
                         g_etile + (size_t)(q * TPI + t + 1) * 65536,
                         65536, bar);
            }
            if (t & 1) PHASE_B(accA, t - 1, lmA);
            else       PHASE_B(accB, t - 1, lmB);
        }
        // ---- final tile epilogue ----
        if (TPI & 1) {                               // TPI=16: last tile in accB
            PHASE_A(accB, TPI - 1, lmB);
            __syncthreads();
            PHASE_B(accB, TPI - 1, lmB);
        } else {
            PHASE_A(accB, TPI - 1, lmB);
            __syncthreads();
            PHASE_B(accB, TPI - 1, lmB);
        }
        #undef MMA_TILE
        #undef PHASE_A
        #undef PHASE_B
    }
}

// ---- exact recheck + z_st + idx + loss (launch #5) -------------------------
__global__ void __launch_bounds__(256)
recheck(const float* __restrict__ z, const float* __restrict__ emb,
        float* __restrict__ out_zst, float* __restrict__ out_idx,
        int write_extra) {
    __shared__ float zbuf[8][260];
    __shared__ double bsum;
    const int tid = threadIdx.x, wid = tid >> 5, lane = tid & 31;
    if (tid == 0) bsum = 0.0;
    __syncthreads();

    double wsum = 0.0;
    for (int it = 0; it < 8; ++it) {
        const int tok = blockIdx.x * 64 + wid * 8 + it;
        const float4* zg = (const float4*)(z + (size_t)tok * HID);
        float4* zb = (float4*)zbuf[wid];
        zb[lane * 2]     = zg[lane * 2];
        zb[lane * 2 + 1] = zg[lane * 2 + 1];
        __syncwarp();

        const float z2e = g_z2[tok];
        ull key = ~0ull;

        unsigned cq[4];
        bool ovf = false;
        #pragma unroll
        for (int q = 0; q < 4; ++q) {
            unsigned c = g_cc4[tok * 4 + q];
            if (c > CAPQ) { ovf = true; c = 0; }
            cq[q] = c;
        }
        const unsigned b1 = cq[0], b2 = b1 + cq[1], b3 = b2 + cq[2];
        const unsigned T = b3 + cq[3];
        for (unsigned i = lane; i < T; i += 32) {
            int q = (i >= b1) + (i >= b2) + (i >= b3);
            unsigned base = (q == 0) ? 0u : ((q == 1) ? b1 : ((q == 2) ? b2 : b3));
            int n = g_cd[(tok * 4 + q) * CAPQ + (i - base)];
            float dot = exact_dot((const float4*)zbuf[wid],
                                  (const float4*)(emb + (size_t)n * HID));
            float dist = (z2e - 2.0f * dot) + __ldg(&g_e2[n]);
            ull k = ((ull)fkey(dist) << 32) | (unsigned)n;
            if (k < key) key = k;
        }
        if (ovf) {
            #pragma unroll
            for (int q = 0; q < 4; ++q) {
                if (g_cc4[tok * 4 + q] <= CAPQ) continue;
                for (int n = q * QCODES + lane; n < (q + 1) * QCODES; n += 32) {
                    float dot = exact_dot((const float4*)zbuf[wid],
                                          (const float4*)(emb + (size_t)n * HID));
                    float dist = (z2e - 2.0f * dot) + __ldg(&g_e2[n]);
                    ull k = ((ull)fkey(dist) << 32) | (unsigned)n;
                    if (k < key) key = k;
                }
            }
        }
        #pragma unroll
        for (int o = 16; o; o >>= 1) {
            ull other = __shfl_down_sync(0xffffffffu, key, o);
            if (other < key) key = other;
        }
        key = __shfl_sync(0xffffffffu, key, 0);
        const unsigned nbest = (unsigned)(key & 0xffffffffull);

        if (lane == 0 && write_extra) out_idx[tok] = (float)nbest;

        const float4* er = (const float4*)(emb + (size_t)nbest * HID);
        float4* outr = (float4*)(out_zst + (size_t)tok * HID);
        #pragma unroll
        for (int qq = 0; qq < 2; ++qq) {
            int j = lane * 2 + qq;
            float4 e = er[j], v = ((const float4*)zbuf[wid])[j];
            float dx = e.x - v.x, dy = e.y - v.y;
            float dz = e.z - v.z, dw = e.w - v.w;
            float4 stv;
            stv.x = v.x + dx; stv.y = v.y + dy;
            stv.z = v.z + dz; stv.w = v.w + dw;
            outr[j] = stv;
            wsum += (double)dx * dx + (double)dy * dy +
                    (double)dz * dz + (double)dw * dw;
        }
        __syncwarp();
    }
    #pragma unroll
    for (int o = 16; o; o >>= 1)
        wsum += __shfl_down_sync(0xffffffffu, wsum, o);
    if (lane == 0) atomicAdd(&bsum, wsum);
    __syncthreads();
    if (tid == 0) atomicAdd(&g_loss, bsum);
}

// ---- finalize losses --------------------------------------------------------
__global__ void finalize_kernel(float* __restrict__ out_loss) {
    float mloss = (float)(g_loss / (double)Z_ST_ELEMS);
    out_loss[0] = mloss;
    out_loss[1] = mloss;
}

// ---- launch -------------------------------------------------------------------
extern "C" void kernel_launch(void* const* d_in, const int* in_sizes, int n_in,
                              void* d_out, int out_size) {
    const float* z   = (const float*)d_in[0];
    const float* emb = (const float*)d_in[1];
    float* out = (float*)d_out;

    cudaFuncSetAttribute(vq_mma, cudaFuncAttributeMaxDynamicSharedMemorySize,
                         SMEM_BYTES);

    int full = (out_size >= FULL_OUT) ? 1 : 0;
    float* out_idx = full ? (out + Z_ST_ELEMS) : nullptr;

    init_kernel<<<TOKENS * 4 / 256, 256>>>();          // launch #1
    prep_e<<<NCODES / 8, 256>>>(emb);                  // launch #2
    prep_z<<<TOKENS / 8, 256>>>(z);                    // launch #3
    vq_mma<<<148, 256, SMEM_BYTES>>>();                // launch #4 (ncu target)
    recheck<<<TOKENS / 64, 256>>>(z, emb, out, out_idx, full);  // #5
    if (full) finalize_kernel<<<1, 1>>>(out + Z_ST_ELEMS + TOKENS);  // #6
}

// round 16
// speedup vs baseline: 1.1497x; 1.1497x over previous
#include <cuda_runtime.h>
#include <cuda_bf16.h>
#include <cstdint>

// ============================================================================
// VQ via mma.sync bf16 (m16n8k16). 148 persistent CTAs (512 thr), queue of
// 1024 (128-token block, quarter) items. NO per-tile block barrier: B-stage
// reuse guarded by consumer "empty" mbarriers (16 warp arrivals), threshold
// shared opportunistically via smem atomicMin. A + B via cp.async.bulk from
// PRE-SWIZZLED images. Exact sequential-fp32-FMA-chain recheck.
// ============================================================================

#define TOKENS   32768
#define HID      256
#define NCODES   8192
#define MT       128
#define NTILE    128
#define QCODES   2048
#define TPI      16                   // tiles per item
#define NITEMS   1024                 // 256 m-blocks * 4 quarters
#define CAPQ     64
#define DELTA    0.03f
#define Z_ST_ELEMS (TOKENS * HID)
#define FULL_OUT   (Z_ST_ELEMS + TOKENS + 2)

typedef unsigned long long ull;

__device__ __align__(128) unsigned char g_zsw[TOKENS * 512];    // 16MB
__device__ __align__(128) unsigned char g_etile[NCODES * 512];  // 4MB
__device__ float    g_e2[NCODES];
__device__ float    g_z2[TOKENS];
__device__ unsigned g_cc4[TOKENS * 4];
__device__ unsigned short g_cd[TOKENS * 4 * CAPQ];
__device__ int      g_queue;
__device__ double   g_loss;

// ---- SMEM layout ----
#define A_OFF   0                        // 128*512 = 65536
#define B_OFF   65536                    // 2 * 65536 -> 196608
#define E2S_OFF 196608                   // 2048 f32 = 8192
#define MK_OFF  204800                   // 128 u32
#define MB_OFF  205312                   // 5 mbarriers (A, full0/1, empty0/1)
#define SITEM   205352
#define SMEM_BYTES 205360

// ---- PTX helpers ----
__device__ __forceinline__ uint32_t smem_u32(const void* p) {
    uint32_t a;
    asm("{ .reg .u64 t; cvta.to.shared.u64 t, %1; cvt.u32.u64 %0, t; }"
        : "=r"(a) : "l"(p));
    return a;
}
__device__ __forceinline__ void cp_async16(uint32_t dst, const void* src) {
    asm volatile("cp.async.cg.shared.global [%0], [%1], 16;\n"
                 :: "r"(dst), "l"(src));
}
#define CP_COMMIT() asm volatile("cp.async.commit_group;" ::: "memory")
#define CP_WAIT0()  asm volatile("cp.async.wait_group 0;" ::: "memory")
#define FENCE_ASYNC() asm volatile("fence.proxy.async.shared::cta;" ::: "memory")

#define MBARRIER_INIT(a, c) \
    asm volatile("mbarrier.init.shared.b64 [%0], %1;" \
                 :: "r"((uint32_t)(a)), "r"((uint32_t)(c)) : "memory")
#define MBARRIER_ARRIVE(a) \
    asm volatile("mbarrier.arrive.shared.b64 _, [%0];" \
                 :: "r"((uint32_t)(a)) : "memory")
#define MBAR_EXPECT(bar, tx) \
    asm volatile("mbarrier.arrive.expect_tx.shared.b64 _, [%0], %1;" \
                 :: "r"((uint32_t)(bar)), "r"((uint32_t)(tx)) : "memory")
#define BULK_G2S(dst, src, sz, bar) \
    asm volatile("cp.async.bulk.shared::cta.global.mbarrier::complete_tx::bytes " \
                 "[%0], [%1], %2, [%3];" \
                 :: "r"((uint32_t)(dst)), "l"(src), "r"((uint32_t)(sz)), \
                    "r"((uint32_t)(bar)) : "memory")
#define MBARRIER_WAIT_PARITY(addr, par) do { \
    uint32_t _m = (uint32_t)(addr), _p = (uint32_t)(par), _d; \
    asm volatile("{\n\t.reg .pred p;\n\t" \
        "mbarrier.try_wait.parity.acquire.cta.shared::cta.b64 p, [%1], %2;\n\t" \
        "selp.b32 %0, 1, 0, p;\n\t}" : "=r"(_d) : "r"(_m), "r"(_p) : "memory"); \
    if (!_d) { \
        asm volatile("{\n\t.reg .pred P1;\n\t" \
            "W%=:\n\t" \
            "mbarrier.try_wait.parity.acquire.cta.shared::cta.b64 P1, [%0], %1, 0x989680;\n\t" \
            "@P1 bra.uni D%=;\n\t" \
            "bra.uni W%=;\n\t" \
            "D%=:\n\t}" :: "r"(_m), "r"(_p) : "memory"); \
    } \
} while (0)

#define LDSM4(r, a) \
    asm volatile("ldmatrix.sync.aligned.m8n8.x4.shared.b16 {%0,%1,%2,%3}, [%4];" \
        : "=r"((r)[0]), "=r"((r)[1]), "=r"((r)[2]), "=r"((r)[3]) : "r"(a))

#define MMA16816(d, a, b0, b1) \
    asm volatile("mma.sync.aligned.m16n8k16.row.col.f32.bf16.bf16.f32 " \
        "{%0,%1,%2,%3}, {%4,%5,%6,%7}, {%8,%9}, {%0,%1,%2,%3};" \
        : "+f"((d)[0]), "+f"((d)[1]), "+f"((d)[2]), "+f"((d)[3]) \
        : "r"((a)[0]), "r"((a)[1]), "r"((a)[2]), "r"((a)[3]), "r"(b0), "r"(b1))

__device__ __forceinline__ unsigned fkey(float f) {
    unsigned u = __float_as_uint(f);
    return (u & 0x80000000u) ? ~u : (u | 0x80000000u);
}
__device__ __forceinline__ float unfkey(unsigned k) {
    return (k & 0x80000000u) ? __uint_as_float(k & 0x7fffffffu)
                             : __uint_as_float(~k);
}
__device__ __forceinline__ unsigned pk2(float a, float b) {
    __nv_bfloat162 t = __floats2bfloat162_rn(a, b);
    return *(unsigned*)&t;
}
// exact sequential fp32 FMA chain over ascending k (reference arithmetic)
__device__ __forceinline__ float exact_dot(const float4* zr, const float4* er) {
    float dot = 0.f;
    #pragma unroll 8
    for (int kk = 0; kk < HID / 4; ++kk) {
        float4 a = zr[kk], b = er[kk];
        dot = fmaf(a.x, b.x, dot);
        dot = fmaf(a.y, b.y, dot);
        dot = fmaf(a.z, b.z, dot);
        dot = fmaf(a.w, b.w, dot);
    }
    return dot;
}

// ---- init (launch #1) ----
__global__ void init_kernel() {
    int i = blockIdx.x * 256 + threadIdx.x;
    g_cc4[i] = 0u;
    if (i == 0) { g_queue = 0; g_loss = 0.0; }
}

// ---- prep kernels: bf16 convert + PRE-SWIZZLE (128-row blocks) + norms ----
__global__ void prep_e(const float* __restrict__ emb) {
    int code = blockIdx.x * 8 + (threadIdx.x >> 5);
    int lane = threadIdx.x & 31;
    const float4* r = (const float4*)(emb + (size_t)code * HID);
    float4 v0 = r[lane * 2], v1 = r[lane * 2 + 1];
    double s = (double)v0.x * v0.x + (double)v0.y * v0.y +
               (double)v0.z * v0.z + (double)v0.w * v0.w +
               (double)v1.x * v1.x + (double)v1.y * v1.y +
               (double)v1.z * v1.z + (double)v1.w * v1.w;
    #pragma unroll
    for (int o = 16; o; o >>= 1) s += __shfl_down_sync(0xffffffffu, s, o);
    if (lane == 0) g_e2[code] = (float)s;
    uint4 pk = make_uint4(pk2(v0.x, v0.y), pk2(v0.z, v0.w),
                          pk2(v1.x, v1.y), pk2(v1.z, v1.w));
    int tt = code >> 7, rr = code & 127;
    *(uint4*)(g_etile + (size_t)tt * 65536 + rr * 512 +
              ((lane ^ (rr & 7)) << 4)) = pk;
}
__global__ void prep_z(const float* __restrict__ z) {
    int tok = blockIdx.x * 8 + (threadIdx.x >> 5);
    int lane = threadIdx.x & 31;
    const float4* r = (const float4*)(z + (size_t)tok * HID);
    float4 v0 = r[lane * 2], v1 = r[lane * 2 + 1];
    double s = (double)v0.x * v0.x + (double)v0.y * v0.y +
               (double)v0.z * v0.z + (double)v0.w * v0.w +
               (double)v1.x * v1.x + (double)v1.y * v1.y +
               (double)v1.z * v1.z + (double)v1.w * v1.w;
    #pragma unroll
    for (int o = 16; o; o >>= 1) s += __shfl_down_sync(0xffffffffu, s, o);
    if (lane == 0) g_z2[tok] = (float)s;
    uint4 pk = make_uint4(pk2(v0.x, v0.y), pk2(v0.z, v0.w),
                          pk2(v1.x, v1.y), pk2(v1.z, v1.w));
    int bb = tok >> 7, rr = tok & 127;
    *(uint4*)(g_zsw + (size_t)bb * 65536 + rr * 512 +
              ((lane ^ (rr & 7)) << 4)) = pk;
}

// ---- main persistent kernel (launch #4) -------------------------------------
__global__ void __launch_bounds__(512, 1)
vq_mma() {
    extern __shared__ char p0[];
    const uint32_t s0 = smem_u32(p0);

    const int tid = threadIdx.x;
    const int lane = tid & 31, wid = tid >> 5;
    const int warpM = wid >> 2, warpN = wid & 3;     // 4M x 4N over 128x128
    const int g = lane >> 2, tg = lane & 3;
    int* sitem = (int*)(p0 + SITEM);
    float* e2s = (float*)(p0 + E2S_OFF);
    unsigned* mk = (unsigned*)(p0 + MK_OFF);         // fkey-packed row minima
    const uint32_t mbA  = s0 + MB_OFF;
    const uint32_t mbF0 = s0 + MB_OFF + 8;           // B full barriers
    const uint32_t mbF1 = s0 + MB_OFF + 16;
    const uint32_t mbE0 = s0 + MB_OFF + 24;          // B empty barriers
    const uint32_t mbE1 = s0 + MB_OFF + 32;

    if (tid == 0) {
        MBARRIER_INIT(mbA, 1);
        MBARRIER_INIT(mbF0, 1);
        MBARRIER_INIT(mbF1, 1);
        MBARRIER_INIT(mbE0, 16);
        MBARRIER_INIT(mbE1, 16);
    }
    __syncthreads();
    FENCE_ASYNC();

    const int r7 = lane & 7, cc = lane >> 4;
    const uint32_t aBase = s0 + A_OFF + (warpM * 32 + (lane & 15)) * 512;
    const uint32_t bBase = s0 + B_OFF + (warpN * 32 + (lane & 15)) * 512;

    int curm = -1, aPar = 0;
    int pc0 = 0, pc1 = 0;                // producer load counts per stage (tid0)
    float z2r[4];
    int rowid[4];

    for (;;) {
        __syncthreads();                 // previous item fully consumed
        if (tid == 0) *sitem = atomicAdd(&g_queue, 1);
        __syncthreads();
        const int item = *sitem;
        if (item >= NITEMS) break;
        const int m = item >> 2, q = item & 3;

        if (tid < 128) mk[tid] = 0xFFFFFFFFu;

        const bool newm = (m != curm);
        if (newm) {
            curm = m;
            if (tid == 0) {
                MBAR_EXPECT(mbA, 65536);
                BULK_G2S(s0 + A_OFF, g_zsw + (size_t)m * 65536, 65536, mbA);
            }
            #pragma unroll
            for (int r4 = 0; r4 < 4; ++r4) {
                int row = warpM * 32 + (r4 >> 1) * 16 + (r4 & 1) * 8 + g;
                rowid[r4] = m * MT + row;
                z2r[r4] = g_z2[rowid[r4]];
            }
        }
        // e2 quarter slice + first two B tiles (producer waits stage recycling)
        cp_async16(s0 + E2S_OFF + tid * 16,
                   (const char*)(g_e2 + q * QCODES) + tid * 16);
        CP_COMMIT();
        if (tid == 0) {
            if (pc0 >= 1) MBARRIER_WAIT_PARITY(mbE0, (pc0 - 1) & 1);
            MBAR_EXPECT(mbF0, 65536);
            BULK_G2S(s0 + B_OFF, g_etile + (size_t)(q * TPI) * 65536,
                     65536, mbF0);
            ++pc0;
            if (pc1 >= 1) MBARRIER_WAIT_PARITY(mbE1, (pc1 - 1) & 1);
            MBAR_EXPECT(mbF1, 65536);
            BULK_G2S(s0 + B_OFF + 65536,
                     g_etile + (size_t)(q * TPI + 1) * 65536, 65536, mbF1);
            ++pc1;
        }
        CP_WAIT0();
        __syncthreads();                 // e2s + mk init visible
        if (newm) { MBARRIER_WAIT_PARITY(mbA, aPar); aPar ^= 1; }

        float rm[4];
        #pragma unroll
        for (int r4 = 0; r4 < 4; ++r4) rm[r4] = __int_as_float(0x7f800000);

        for (int t = 0; t < TPI; ++t) {
            MBARRIER_WAIT_PARITY((t & 1) ? mbF1 : mbF0, (t >> 1) & 1);

            float acc[2][4][4];
            #pragma unroll
            for (int a = 0; a < 2; ++a)
                #pragma unroll
                for (int b = 0; b < 4; ++b)
                    #pragma unroll
                    for (int c = 0; c < 4; ++c) acc[a][b][c] = 0.f;

            const uint32_t bT = bBase + (t & 1) * 65536;

            #pragma unroll
            for (int ks = 0; ks < 16; ++ks) {
                const uint32_t off = (uint32_t)(((2 * ks + cc) ^ r7) << 4);
                uint32_t A0[4], A1[4], B0[4], B1[4];
                LDSM4(A0, aBase + off);
                LDSM4(A1, aBase + 8192 + off);
                LDSM4(B0, bT + off);
                LDSM4(B1, bT + 8192 + off);
                MMA16816(acc[0][0], A0, B0[0], B0[2]);
                MMA16816(acc[0][1], A0, B0[1], B0[3]);
                MMA16816(acc[0][2], A0, B1[0], B1[2]);
                MMA16816(acc[0][3], A0, B1[1], B1[3]);
                MMA16816(acc[1][0], A1, B0[0], B0[2]);
                MMA16816(acc[1][1], A1, B0[1], B0[3]);
                MMA16816(acc[1][2], A1, B1[0], B1[2]);
                MMA16816(acc[1][3], A1, B1[1], B1[3]);
            }
            // stage data fully consumed into registers -> arrive (1 per warp)
            if (lane == 0) MBARRIER_ARRIVE((t & 1) ? mbE1 : mbE0);

            // producer: load tile t+2 into stage t&1 once its consumers drain
            if (tid == 0 && t + 2 < TPI) {
                if (t & 1) {
                    if (pc1 >= 1) MBARRIER_WAIT_PARITY(mbE1, (pc1 - 1) & 1);
                    MBAR_EXPECT(mbF1, 65536);
                    BULK_G2S(s0 + B_OFF + 65536,
                             g_etile + (size_t)(q * TPI + t + 2) * 65536,
                             65536, mbF1);
                    ++pc1;
                } else {
                    if (pc0 >= 1) MBARRIER_WAIT_PARITY(mbE0, (pc0 - 1) & 1);
                    MBAR_EXPECT(mbF0, 65536);
                    BULK_G2S(s0 + B_OFF,
                             g_etile + (size_t)(q * TPI + t + 2) * 65536,
                             65536, mbF0);
                    ++pc0;
                }
            }

            // ---- fused epilogue (no block barrier) ----
            float e2c[8];
            #pragma unroll
            for (int nf = 0; nf < 4; ++nf) {
                float2 v = *(const float2*)&e2s[t * NTILE + warpN * 32 +
                                                nf * 8 + tg * 2];
                e2c[nf * 2]     = v.x;
                e2c[nf * 2 + 1] = v.y;
            }
            #pragma unroll
            for (int mf = 0; mf < 2; ++mf)
                #pragma unroll
                for (int h = 0; h < 2; ++h) {
                    const int r4 = mf * 2 + h;
                    const float z2t = z2r[r4];
                    float lmin = __int_as_float(0x7f800000);
                    #pragma unroll
                    for (int nf = 0; nf < 4; ++nf)
                        #pragma unroll
                        for (int e = 0; e < 2; ++e) {
                            float dist = fmaf(-2.f, acc[mf][nf][h * 2 + e],
                                              z2t) + e2c[nf * 2 + e];
                            acc[mf][nf][h * 2 + e] = dist;
                            lmin = fminf(lmin, dist);
                        }
                    lmin = fminf(lmin, __shfl_xor_sync(0xffffffffu, lmin, 1));
                    lmin = fminf(lmin, __shfl_xor_sync(0xffffffffu, lmin, 2));
                    const int row = warpM * 32 + mf * 16 + h * 8 + g;
                    unsigned nk = fkey(lmin);
                    unsigned cur = 0xFFFFFFFFu;
                    if (tg == 0) cur = atomicMin(&mk[row], nk);
                    cur = __shfl_sync(0xffffffffu, cur, lane & ~3);
                    // unfkey(0xFFFFFFFF) = NaN; fminf filters it out
                    float gmin = fminf(fminf(unfkey(cur), lmin), rm[r4]);
                    rm[r4] = gmin;
                    const float thr = gmin + DELTA;
                    if (lmin <= thr) {
                        #pragma unroll
                        for (int nf = 0; nf < 4; ++nf)
                            #pragma unroll
                            for (int e = 0; e < 2; ++e)
                                if (acc[mf][nf][h * 2 + e] <= thr) {
                                    unsigned pos = atomicAdd(
                                        &g_cc4[rowid[r4] * 4 + q], 1u);
                                    if (pos < CAPQ)
                                        g_cd[(rowid[r4] * 4 + q) * CAPQ + pos]
                                            = (unsigned short)(q * QCODES +
                                                t * NTILE + warpN * 32 +
                                                nf * 8 + tg * 2 + e);
                                }
                    }
                }
        }
    }
}

// ---- exact recheck + z_st + idx + loss (launch #5) -------------------------
__global__ void __launch_bounds__(256)
recheck(const float* __restrict__ z, const float* __restrict__ emb,
        float* __restrict__ out_zst, float* __restrict__ out_idx,
        int write_extra) {
    __shared__ float zbuf[8][260];
    __shared__ double bsum;
    const int tid = threadIdx.x, wid = tid >> 5, lane = tid & 31;
    if (tid == 0) bsum = 0.0;
    __syncthreads();

    double wsum = 0.0;
    for (int it = 0; it < 8; ++it) {
        const int tok = blockIdx.x * 64 + wid * 8 + it;
        const float4* zg = (const float4*)(z + (size_t)tok * HID);
        float4* zb = (float4*)zbuf[wid];
        zb[lane * 2]     = zg[lane * 2];
        zb[lane * 2 + 1] = zg[lane * 2 + 1];
        __syncwarp();

        const float z2e = g_z2[tok];
        ull key = ~0ull;

        unsigned cq[4];
        bool ovf = false;
        #pragma unroll
        for (int q = 0; q < 4; ++q) {
            unsigned c = g_cc4[tok * 4 + q];
            if (c > CAPQ) { ovf = true; c = 0; }
            cq[q] = c;
        }
        const unsigned b1 = cq[0], b2 = b1 + cq[1], b3 = b2 + cq[2];
        const unsigned T = b3 + cq[3];
        for (unsigned i = lane; i < T; i += 32) {
            int q = (i >= b1) + (i >= b2) + (i >= b3);
            unsigned base = (q == 0) ? 0u : ((q == 1) ? b1 : ((q == 2) ? b2 : b3));
            int n = g_cd[(tok * 4 + q) * CAPQ + (i - base)];
            float dot = exact_dot((const float4*)zbuf[wid],
                                  (const float4*)(emb + (size_t)n * HID));
            float dist = (z2e - 2.0f * dot) + __ldg(&g_e2[n]);
            ull k = ((ull)fkey(dist) << 32) | (unsigned)n;
            if (k < key) key = k;
        }
        if (ovf) {
            #pragma unroll
            for (int q = 0; q < 4; ++q) {
                if (g_cc4[tok * 4 + q] <= CAPQ) continue;
                for (int n = q * QCODES + lane; n < (q + 1) * QCODES; n += 32) {
                    float dot = exact_dot((const float4*)zbuf[wid],
                                          (const float4*)(emb + (size_t)n * HID));
                    float dist = (z2e - 2.0f * dot) + __ldg(&g_e2[n]);
                    ull k = ((ull)fkey(dist) << 32) | (unsigned)n;
                    if (k < key) key = k;
                }
            }
        }
        #pragma unroll
        for (int o = 16; o; o >>= 1) {
            ull other = __shfl_down_sync(0xffffffffu, key, o);
            if (other < key) key = other;
        }
        key = __shfl_sync(0xffffffffu, key, 0);
        const unsigned nbest = (unsigned)(key & 0xffffffffull);

        if (lane == 0 && write_extra) out_idx[tok] = (float)nbest;

        const float4* er = (const float4*)(emb + (size_t)nbest * HID);
        float4* outr = (float4*)(out_zst + (size_t)tok * HID);
        #pragma unroll
        for (int qq = 0; qq < 2; ++qq) {
            int j = lane * 2 + qq;
            float4 e = er[j], v = ((const float4*)zbuf[wid])[j];
            float dx = e.x - v.x, dy = e.y - v.y;
            float dz = e.z - v.z, dw = e.w - v.w;
            float4 stv;
            stv.x = v.x + dx; stv.y = v.y + dy;
            stv.z = v.z + dz; stv.w = v.w + dw;
            outr[j] = stv;
            wsum += (double)dx * dx + (double)dy * dy +
                    (double)dz * dz + (double)dw * dw;
        }
        __syncwarp();
    }
    #pragma unroll
    for (int o = 16; o; o >>= 1)
        wsum += __shfl_down_sync(0xffffffffu, wsum, o);
    if (lane == 0) atomicAdd(&bsum, wsum);
    __syncthreads();
    if (tid == 0) atomicAdd(&g_loss, bsum);
}

// ---- finalize losses --------------------------------------------------------
__global__ void finalize_kernel(float* __restrict__ out_loss) {
    float mloss = (float)(g_loss / (double)Z_ST_ELEMS);
    out_loss[0] = mloss;
    out_loss[1] = mloss;
}

// ---- launch -------------------------------------------------------------------
extern "C" void kernel_launch(void* const* d_in, const int* in_sizes, int n_in,
                              void* d_out, int out_size) {
    const float* z   = (const float*)d_in[0];
    const float* emb = (const float*)d_in[1];
    float* out = (float*)d_out;

    cudaFuncSetAttribute(vq_mma, cudaFuncAttributeMaxDynamicSharedMemorySize,
                         SMEM_BYTES);

    int full = (out_size >= FULL_OUT) ? 1 : 0;
    float* out_idx = full ? (out + Z_ST_ELEMS) : nullptr;

    init_kernel<<<TOKENS * 4 / 256, 256>>>();          // launch #1
    prep_e<<<NCODES / 8, 256>>>(emb);                  // launch #2
    prep_z<<<TOKENS / 8, 256>>>(z);                    // launch #3
    vq_mma<<<148, 512, SMEM_BYTES>>>();                // launch #4 (ncu target)
    recheck<<<TOKENS / 64, 256>>>(z, emb, out, out_idx, full);  // #5
    if (full) finalize_kernel<<<1, 1>>>(out + Z_ST_ELEMS + TOKENS);  // #6
}

// round 17
// speedup vs baseline: 1.3408x; 1.1662x over previous
#include <cuda_runtime.h>
#include <cuda_bf16.h>
#include <cstdint>

// ============================================================================
// VQ via mma.sync bf16 (m16n8k16). 148 persistent CTAs, queue of 1024
// (128-token block, quarter) items. A + B via cp.async.bulk from PRE-SWIZZLED
// images. Two-phase tile epilogue, cross-CTA threshold seeding via global
// per-token min, candidates stored WITH approx dist -> filtered exact
// sequential-fp32-FMA-chain recheck (bit-identical to reference).
// ============================================================================

#define TOKENS   32768
#define HID      256
#define NCODES   8192
#define MT       128
#define NTILE    128
#define QCODES   2048
#define TPI      16                   // tiles per item
#define NITEMS   1024                 // 256 m-blocks * 4 quarters
#define CAPQ     64
#define DELTA    0.03f
#define Z_ST_ELEMS (TOKENS * HID)
#define FULL_OUT   (Z_ST_ELEMS + TOKENS + 2)

typedef unsigned long long ull;

__device__ __align__(128) unsigned char g_zsw[TOKENS * 512];    // 16MB
__device__ __align__(128) unsigned char g_etile[NCODES * 512];  // 4MB
__device__ float    g_e2[NCODES];
__device__ float    g_z2[TOKENS];
__device__ unsigned g_mk[TOKENS];          // fkey-packed global approx min
__device__ unsigned g_cc4[TOKENS * 4];
__device__ ull      g_cd[TOKENS * 4 * CAPQ];   // (fkey(dist)<<32)|code
__device__ int      g_queue;
__device__ double   g_loss;

// ---- SMEM layout ----
#define A_OFF   0                        // 128*512 = 65536
#define B_OFF   65536                    // 2 * 65536 -> 196608
#define E2S_OFF 196608                   // 2048 f32 = 8192
#define MKP_OFF 204800                   // 2 parity * 4 warpN * 128 f32 = 4096
#define MB_OFF  208896                   // 3 mbarriers
#define SITEM   208920
#define SMEM_BYTES 208928

// ---- PTX helpers ----
__device__ __forceinline__ uint32_t smem_u32(const void* p) {
    uint32_t a;
    asm("{ .reg .u64 t; cvta.to.shared.u64 t, %1; cvt.u32.u64 %0, t; }"
        : "=r"(a) : "l"(p));
    return a;
}
__device__ __forceinline__ void cp_async16(uint32_t dst, const void* src) {
    asm volatile("cp.async.cg.shared.global [%0], [%1], 16;\n"
                 :: "r"(dst), "l"(src));
}
#define CP_COMMIT() asm volatile("cp.async.commit_group;" ::: "memory")
#define CP_WAIT0()  asm volatile("cp.async.wait_group 0;" ::: "memory")
#define FENCE_ASYNC() asm volatile("fence.proxy.async.shared::cta;" ::: "memory")

#define MBARRIER_INIT(a, c) \
    asm volatile("mbarrier.init.shared.b64 [%0], %1;" \
                 :: "r"((uint32_t)(a)), "r"((uint32_t)(c)) : "memory")
#define MBAR_EXPECT(bar, tx) \
    asm volatile("mbarrier.arrive.expect_tx.shared.b64 _, [%0], %1;" \
                 :: "r"((uint32_t)(bar)), "r"((uint32_t)(tx)) : "memory")
#define BULK_G2S(dst, src, sz, bar) \
    asm volatile("cp.async.bulk.shared::cta.global.mbarrier::complete_tx::bytes " \
                 "[%0], [%1], %2, [%3];" \
                 :: "r"((uint32_t)(dst)), "l"(src), "r"((uint32_t)(sz)), \
                    "r"((uint32_t)(bar)) : "memory")
#define MBARRIER_WAIT_PARITY(addr, par) do { \
    uint32_t _m = (uint32_t)(addr), _p = (uint32_t)(par), _d; \
    asm volatile("{\n\t.reg .pred p;\n\t" \
        "mbarrier.try_wait.parity.acquire.cta.shared::cta.b64 p, [%1], %2;\n\t" \
        "selp.b32 %0, 1, 0, p;\n\t}" : "=r"(_d) : "r"(_m), "r"(_p) : "memory"); \
    if (!_d) { \
        asm volatile("{\n\t.reg .pred P1;\n\t" \
            "W%=:\n\t" \
            "mbarrier.try_wait.parity.acquire.cta.shared::cta.b64 P1, [%0], %1, 0x989680;\n\t" \
            "@P1 bra.uni D%=;\n\t" \
            "bra.uni W%=;\n\t" \
            "D%=:\n\t}" :: "r"(_m), "r"(_p) : "memory"); \
    } \
} while (0)

#define LDSM4(r, a) \
    asm volatile("ldmatrix.sync.aligned.m8n8.x4.shared.b16 {%0,%1,%2,%3}, [%4];" \
        : "=r"((r)[0]), "=r"((r)[1]), "=r"((r)[2]), "=r"((r)[3]) : "r"(a))

#define MMA16816(d, a, b0, b1) \
    asm volatile("mma.sync.aligned.m16n8k16.row.col.f32.bf16.bf16.f32 " \
        "{%0,%1,%2,%3}, {%4,%5,%6,%7}, {%8,%9}, {%0,%1,%2,%3};" \
        : "+f"((d)[0]), "+f"((d)[1]), "+f"((d)[2]), "+f"((d)[3]) \
        : "r"((a)[0]), "r"((a)[1]), "r"((a)[2]), "r"((a)[3]), "r"(b0), "r"(b1))

__device__ __forceinline__ unsigned fkey(float f) {
    unsigned u = __float_as_uint(f);
    return (u & 0x80000000u) ? ~u : (u | 0x80000000u);
}
__device__ __forceinline__ float unfkey(unsigned k) {
    return (k & 0x80000000u) ? __uint_as_float(k & 0x7fffffffu)
                             : __uint_as_float(~k);
}
__device__ __forceinline__ unsigned pk2(float a, float b) {
    __nv_bfloat162 t = __floats2bfloat162_rn(a, b);
    return *(unsigned*)&t;
}
// exact sequential fp32 FMA chain over ascending k (reference arithmetic)
__device__ __forceinline__ float exact_dot(const float4* zr, const float4* er) {
    float dot = 0.f;
    #pragma unroll 8
    for (int kk = 0; kk < HID / 4; ++kk) {
        float4 a = zr[kk], b = er[kk];
        dot = fmaf(a.x, b.x, dot);
        dot = fmaf(a.y, b.y, dot);
        dot = fmaf(a.z, b.z, dot);
        dot = fmaf(a.w, b.w, dot);
    }
    return dot;
}

// ---- init (launch #1) ----
__global__ void init_kernel() {
    int i = blockIdx.x * 256 + threadIdx.x;
    g_cc4[i] = 0u;
    if (i < TOKENS) g_mk[i] = 0xFFFFFFFFu;
    if (i == 0) { g_queue = 0; g_loss = 0.0; }
}

// ---- prep kernels: bf16 convert + PRE-SWIZZLE (128-row blocks) + norms ----
__global__ void prep_e(const float* __restrict__ emb) {
    int code = blockIdx.x * 8 + (threadIdx.x >> 5);
    int lane = threadIdx.x & 31;
    const float4* r = (const float4*)(emb + (size_t)code * HID);
    float4 v0 = r[lane * 2], v1 = r[lane * 2 + 1];
    double s = (double)v0.x * v0.x + (double)v0.y * v0.y +
               (double)v0.z * v0.z + (double)v0.w * v0.w +
               (double)v1.x * v1.x + (double)v1.y * v1.y +
               (double)v1.z * v1.z + (double)v1.w * v1.w;
    #pragma unroll
    for (int o = 16; o; o >>= 1) s += __shfl_down_sync(0xffffffffu, s, o);
    if (lane == 0) g_e2[code] = (float)s;
    uint4 pk = make_uint4(pk2(v0.x, v0.y), pk2(v0.z, v0.w),
                          pk2(v1.x, v1.y), pk2(v1.z, v1.w));
    int tt = code >> 7, rr = code & 127;
    *(uint4*)(g_etile + (size_t)tt * 65536 + rr * 512 +
              ((lane ^ (rr & 7)) << 4)) = pk;
}
__global__ void prep_z(const float* __restrict__ z) {
    int tok = blockIdx.x * 8 + (threadIdx.x >> 5);
    int lane = threadIdx.x & 31;
    const float4* r = (const float4*)(z + (size_t)tok * HID);
    float4 v0 = r[lane * 2], v1 = r[lane * 2 + 1];
    double s = (double)v0.x * v0.x + (double)v0.y * v0.y +
               (double)v0.z * v0.z + (double)v0.w * v0.w +
               (double)v1.x * v1.x + (double)v1.y * v1.y +
               (double)v1.z * v1.z + (double)v1.w * v1.w;
    #pragma unroll
    for (int o = 16; o; o >>= 1) s += __shfl_down_sync(0xffffffffu, s, o);
    if (lane == 0) g_z2[tok] = (float)s;
    uint4 pk = make_uint4(pk2(v0.x, v0.y), pk2(v0.z, v0.w),
                          pk2(v1.x, v1.y), pk2(v1.z, v1.w));
    int bb = tok >> 7, rr = tok & 127;
    *(uint4*)(g_zsw + (size_t)bb * 65536 + rr * 512 +
              ((lane ^ (rr & 7)) << 4)) = pk;
}

// ---- main persistent kernel (launch #4) -------------------------------------
__global__ void __launch_bounds__(512, 1)
vq_mma() {
    extern __shared__ char p0[];
    const uint32_t s0 = smem_u32(p0);

    const int tid = threadIdx.x;
    const int lane = tid & 31, wid = tid >> 5;
    const int warpM = wid >> 2, warpN = wid & 3;     // 4M x 4N over 128x128
    const int g = lane >> 2, tg = lane & 3;
    int* sitem = (int*)(p0 + SITEM);
    float* e2s = (float*)(p0 + E2S_OFF);
    float* mkp = (float*)(p0 + MKP_OFF);             // [parity][warpN][128]
    const uint32_t mbA  = s0 + MB_OFF;
    const uint32_t mbB0 = s0 + MB_OFF + 8;
    const uint32_t mbB1 = s0 + MB_OFF + 16;

    if (tid == 0) {
        MBARRIER_INIT(mbA, 1);
        MBARRIER_INIT(mbB0, 1);
        MBARRIER_INIT(mbB1, 1);
    }
    __syncthreads();
    FENCE_ASYNC();

    const int r7 = lane & 7, cc = lane >> 4;
    const uint32_t aBase = s0 + A_OFF + (warpM * 32 + (lane & 15)) * 512;
    const uint32_t bBase = s0 + B_OFF + (warpN * 32 + (lane & 15)) * 512;

    int curm = -1, aPar = 0;
    float z2r[4];
    int rowid[4];

    for (;;) {
        __syncthreads();                 // previous item fully consumed
        if (tid == 0) *sitem = atomicAdd(&g_queue, 1);
        __syncthreads();
        const int item = *sitem;
        if (item >= NITEMS) break;
        const int m = item >> 2, q = item & 3;

        const bool newm = (m != curm);
        if (newm) {
            curm = m;
            if (tid == 0) {
                MBAR_EXPECT(mbA, 65536);
                BULK_G2S(s0 + A_OFF, g_zsw + (size_t)m * 65536, 65536, mbA);
            }
            #pragma unroll
            for (int r4 = 0; r4 < 4; ++r4) {
                int row = warpM * 32 + (r4 >> 1) * 16 + (r4 & 1) * 8 + g;
                rowid[r4] = m * MT + row;
                z2r[r4] = g_z2[rowid[r4]];
            }
        }
        // e2 quarter slice + first two B tiles
        cp_async16(s0 + E2S_OFF + tid * 16,
                   (const char*)(g_e2 + q * QCODES) + tid * 16);
        CP_COMMIT();
        if (tid == 0) {
            MBAR_EXPECT(mbB0, 65536);
            BULK_G2S(s0 + B_OFF, g_etile + (size_t)(q * TPI) * 65536,
                     65536, mbB0);
            MBAR_EXPECT(mbB1, 65536);
            BULK_G2S(s0 + B_OFF + 65536,
                     g_etile + (size_t)(q * TPI + 1) * 65536, 65536, mbB1);
        }
        CP_WAIT0();
        __syncthreads();                 // e2s visible to all threads
        if (newm) { MBARRIER_WAIT_PARITY(mbA, aPar); aPar ^= 1; }

        // seed running min from global per-token min (cross-CTA sharing);
        // unfkey(0xFFFFFFFF) = NaN; fminf below filters NaN.
        float rm[4];
        #pragma unroll
        for (int r4 = 0; r4 < 4; ++r4)
            rm[r4] = unfkey(__ldcg(&g_mk[rowid[r4]]));

        for (int t = 0; t < TPI; ++t) {
            MBARRIER_WAIT_PARITY((t & 1) ? mbB1 : mbB0, (t >> 1) & 1);

            float e2c[8];
            #pragma unroll
            for (int nf = 0; nf < 4; ++nf) {
                float2 v = *(const float2*)&e2s[t * NTILE + warpN * 32 +
                                                nf * 8 + tg * 2];
                e2c[nf * 2]     = v.x;
                e2c[nf * 2 + 1] = v.y;
            }

            float acc[2][4][4];
            #pragma unroll
            for (int a = 0; a < 2; ++a)
                #pragma unroll
                for (int b = 0; b < 4; ++b)
                    #pragma unroll
                    for (int c = 0; c < 4; ++c) acc[a][b][c] = 0.f;

            const uint32_t bT = bBase + (t & 1) * 65536;

            #pragma unroll
            for (int ks = 0; ks < 16; ++ks) {
                const uint32_t off = (uint32_t)(((2 * ks + cc) ^ r7) << 4);
                uint32_t A0[4], A1[4], B0[4], B1[4];
                LDSM4(A0, aBase + off);
                LDSM4(A1, aBase + 8192 + off);
                LDSM4(B0, bT + off);
                LDSM4(B1, bT + 8192 + off);
                MMA16816(acc[0][0], A0, B0[0], B0[2]);
                MMA16816(acc[0][1], A0, B0[1], B0[3]);
                MMA16816(acc[0][2], A0, B1[0], B1[2]);
                MMA16816(acc[0][3], A0, B1[1], B1[3]);
                MMA16816(acc[1][0], A1, B0[0], B0[2]);
                MMA16816(acc[1][1], A1, B0[1], B0[3]);
                MMA16816(acc[1][2], A1, B1[0], B1[2]);
                MMA16816(acc[1][3], A1, B1[1], B1[3]);
            }

            // ---- phase A: dists + warp-block row min -> mkp[parity] ----
            float lmin4[4];
            #pragma unroll
            for (int mf = 0; mf < 2; ++mf)
                #pragma unroll
                for (int h = 0; h < 2; ++h) {
                    const int r4 = mf * 2 + h;
                    const float z2t = z2r[r4];
                    float lmin = __int_as_float(0x7f800000);
                    #pragma unroll
                    for (int nf = 0; nf < 4; ++nf)
                        #pragma unroll
                        for (int e = 0; e < 2; ++e) {
                            float dist = fmaf(-2.f, acc[mf][nf][h * 2 + e],
                                              z2t) + e2c[nf * 2 + e];
                            acc[mf][nf][h * 2 + e] = dist;
                            lmin = fminf(lmin, dist);
                        }
                    lmin = fminf(lmin, __shfl_xor_sync(0xffffffffu, lmin, 1));
                    lmin = fminf(lmin, __shfl_xor_sync(0xffffffffu, lmin, 2));
                    lmin4[r4] = lmin;
                    const int row = warpM * 32 + mf * 16 + h * 8 + g;
                    if (tg == 0)
                        mkp[(t & 1) * 512 + warpN * 128 + row] = lmin;
                }
            __syncthreads();             // the single per-tile barrier

            // prefetch B tile t+2 into the stage just freed (t&1)
            if (tid == 0 && t + 2 < TPI) {
                const uint32_t bar = (t & 1) ? mbB1 : mbB0;
                MBAR_EXPECT(bar, 65536);
                BULK_G2S(s0 + B_OFF + (t & 1) * 65536,
                         g_etile + (size_t)(q * TPI + t + 2) * 65536,
                         65536, bar);
            }

            // ---- phase B: early-out candidate append (dist stored w/ code)
            const float* mk0 = mkp + (t & 1) * 512;
            #pragma unroll
            for (int mf = 0; mf < 2; ++mf)
                #pragma unroll
                for (int h = 0; h < 2; ++h) {
                    const int r4 = mf * 2 + h;
                    const int row = warpM * 32 + mf * 16 + h * 8 + g;
                    float tmin = fminf(fminf(mk0[row], mk0[128 + row]),
                                       fminf(mk0[256 + row], mk0[384 + row]));
                    rm[r4] = fminf(tmin, rm[r4]);    // NaN-seed filtered here
                    const float thr = rm[r4] + DELTA;
                    if (lmin4[r4] <= thr) {
                        #pragma unroll
                        for (int nf = 0; nf < 4; ++nf)
                            #pragma unroll
                            for (int e = 0; e < 2; ++e) {
                                float dv = acc[mf][nf][h * 2 + e];
                                if (dv <= thr) {
                                    unsigned pos = atomicAdd(
                                        &g_cc4[rowid[r4] * 4 + q], 1u);
                                    if (pos < CAPQ)
                                        g_cd[(rowid[r4] * 4 + q) * CAPQ + pos]
                                            = ((ull)fkey(dv) << 32) |
                                              (unsigned)(q * QCODES +
                                                t * NTILE + warpN * 32 +
                                                nf * 8 + tg * 2 + e);
                                }
                            }
                    }
                }
        }
        // publish this item's per-row min to the global per-token min
        #pragma unroll
        for (int r4 = 0; r4 < 4; ++r4)
            if (tg == 0 && warpN == 0)
                atomicMin(&g_mk[rowid[r4]], fkey(rm[r4]));
    }
}

// ---- filtered exact recheck + z_st + idx + loss (launch #5) -----------------
__global__ void __launch_bounds__(256)
recheck(const float* __restrict__ z, const float* __restrict__ emb,
        float* __restrict__ out_zst, float* __restrict__ out_idx,
        int write_extra) {
    __shared__ float zbuf[8][260];
    __shared__ double bsum;
    const int tid = threadIdx.x, wid = tid >> 5, lane = tid & 31;
    if (tid == 0) bsum = 0.0;
    __syncthreads();

    double wsum = 0.0;
    for (int it = 0; it < 8; ++it) {
        const int tok = blockIdx.x * 64 + wid * 8 + it;
        const float4* zg = (const float4*)(z + (size_t)tok * HID);
        float4* zb = (float4*)zbuf[wid];
        zb[lane * 2]     = zg[lane * 2];
        zb[lane * 2 + 1] = zg[lane * 2 + 1];
        __syncwarp();

        const float z2e = g_z2[tok];
        // global approx min -> filter threshold (contains exact argmin:
        // dtilde(n*) <= dtilde_min + 2*eps <= thr, DELTA >= 2*eps)
        const float thr = unfkey(g_mk[tok]) + DELTA;
        ull key = ~0ull;

        unsigned cq[4];
        bool ovf = false;
        #pragma unroll
        for (int q = 0; q < 4; ++q) {
            unsigned c = g_cc4[tok * 4 + q];
            if (c > CAPQ) { ovf = true; c = 0; }
            cq[q] = c;
        }
        const unsigned b1 = cq[0], b2 = b1 + cq[1], b3 = b2 + cq[2];
        const unsigned T = b3 + cq[3];
        for (unsigned i = lane; i < T; i += 32) {
            int q = (i >= b1) + (i >= b2) + (i >= b3);
            unsigned base = (q == 0) ? 0u : ((q == 1) ? b1 : ((q == 2) ? b2 : b3));
            ull cdv = g_cd[(tok * 4 + q) * CAPQ + (i - base)];
            if (unfkey((unsigned)(cdv >> 32)) > thr) continue;  // filtered out
            int n = (int)(cdv & 0xffffffffull);
            float dot = exact_dot((const float4*)zbuf[wid],
                                  (const float4*)(emb + (size_t)n * HID));
            float dist = (z2e - 2.0f * dot) + __ldg(&g_e2[n]);
            ull k = ((ull)fkey(dist) << 32) | (unsigned)n;
            if (k < key) key = k;
        }
        if (ovf) {
            #pragma unroll
            for (int q = 0; q < 4; ++q) {
                if (g_cc4[tok * 4 + q] <= CAPQ) continue;
                for (int n = q * QCODES + lane; n < (q + 1) * QCODES; n += 32) {
                    float dot = exact_dot((const float4*)zbuf[wid],
                                          (const float4*)(emb + (size_t)n * HID));
                    float dist = (z2e - 2.0f * dot) + __ldg(&g_e2[n]);
                    ull k = ((ull)fkey(dist) << 32) | (unsigned)n;
                    if (k < key) key = k;
                }
            }
        }
        #pragma unroll
        for (int o = 16; o; o >>= 1) {
            ull other = __shfl_down_sync(0xffffffffu, key, o);
            if (other < key) key = other;
        }
        key = __shfl_sync(0xffffffffu, key, 0);
        const unsigned nbest = (unsigned)(key & 0xffffffffull);

        if (lane == 0 && write_extra) out_idx[tok] = (float)nbest;

        const float4* er = (const float4*)(emb + (size_t)nbest * HID);
        float4* outr = (float4*)(out_zst + (size_t)tok * HID);
        #pragma unroll
        for (int qq = 0; qq < 2; ++qq) {
            int j = lane * 2 + qq;
            float4 e = er[j], v = ((const float4*)zbuf[wid])[j];
            float dx = e.x - v.x, dy = e.y - v.y;
            float dz = e.z - v.z, dw = e.w - v.w;
            float4 stv;
            stv.x = v.x + dx; stv.y = v.y + dy;
            stv.z = v.z + dz; stv.w = v.w + dw;
            outr[j] = stv;
            wsum += (double)dx * dx + (double)dy * dy +
                    (double)dz * dz + (double)dw * dw;
        }
        __syncwarp();
    }
    #pragma unroll
    for (int o = 16; o; o >>= 1)
        wsum += __shfl_down_sync(0xffffffffu, wsum, o);
    if (lane == 0) atomicAdd(&bsum, wsum);
    __syncthreads();
    if (tid == 0) atomicAdd(&g_loss, bsum);
}

// ---- finalize losses --------------------------------------------------------
__global__ void finalize_kernel(float* __restrict__ out_loss) {
    float mloss = (float)(g_loss / (double)Z_ST_ELEMS);
    out_loss[0] = mloss;
    out_loss[1] = mloss;
}

// ---- launch -------------------------------------------------------------------
extern "C" void kernel_launch(void* const* d_in, const int* in_sizes, int n_in,
                              void* d_out, int out_size) {
    const float* z   = (const float*)d_in[0];
    const float* emb = (const float*)d_in[1];
    float* out = (float*)d_out;

    cudaFuncSetAttribute(vq_mma, cudaFuncAttributeMaxDynamicSharedMemorySize,
                         SMEM_BYTES);

    int full = (out_size >= FULL_OUT) ? 1 : 0;
    float* out_idx = full ? (out + Z_ST_ELEMS) : nullptr;

    init_kernel<<<TOKENS * 4 / 256, 256>>>();          // launch #1
    prep_e<<<NCODES / 8, 256>>>(emb);                  // launch #2
    prep_z<<<TOKENS / 8, 256>>>(z);                    // launch #3
    vq_mma<<<148, 512, SMEM_BYTES>>>();                // launch #4 (ncu target)
    recheck<<<TOKENS / 64, 256>>>(z, emb, out, out_idx, full);  // #5
    if (full) finalize_kernel<<<1, 1>>>(out + Z_ST_ELEMS + TOKENS);  // #6
}